// round 10
// baseline (speedup 1.0000x reference)
#include <cuda_runtime.h>

typedef unsigned long long u64;

// Packed dual-fp32 ops (FFMA2 in SASS — only reachable via PTX f32x2).
__device__ __forceinline__ u64 ffma2(u64 a, u64 b, u64 c) {
    u64 d;
    asm("fma.rn.f32x2 %0, %1, %2, %3;" : "=l"(d) : "l"(a), "l"(b), "l"(c));
    return d;
}
__device__ __forceinline__ u64 fadd2(u64 a, u64 b) {
    u64 d;
    asm("add.rn.f32x2 %0, %1, %2;" : "=l"(d) : "l"(a), "l"(b));
    return d;
}

// Dynamic smem layout (floats):
//   xs  [64*60]   : W-rolled, zero-padded row slab; xs[i][m+j] = patches[..,j,m]
//   xs2 [64*60]   : shifted shadow, xs2[i][u] = xs[i][u+1] (aligned odd pairs)
//   Ws2 [64*48*2] : W duplicated as (w,w) float2 pairs, layout [i][k*3+j]
//   ps  [8*112*8] : per-slice partial sums (slice stride = 896 floats = 448 u64)
static constexpr int XS_OFF  = 0;
static constexpr int XS2_OFF = 64 * 60;            // 3840
static constexpr int WS2_OFF = XS2_OFF + 64 * 60;  // 7680
static constexpr int PS_OFF  = WS2_OFF + 64 * 96;  // 13824
static constexpr int SMEM_FLOATS = PS_OFF + 8 * 112 * 8;   // 20992
static constexpr int SMEM_BYTES  = SMEM_FLOATS * 4;        // 83968

static constexpr int PS_SLICE_U64 = (112 * 8) / 2;         // 448 u64 per slice

__global__ __launch_bounds__(1024, 1)
void shiftconv_kernel(const float* __restrict__ x,
                      const float* __restrict__ Wg,
                      float* __restrict__ y)
{
    extern __shared__ float sm[];
    float* xs  = sm + XS_OFF;
    float* xs2 = sm + XS2_OFF;
    float* Ws2 = sm + WS2_OFF;
    float* ps  = sm + PS_OFF;

    const int n_src = blockIdx.x;            // 0..55
    const int o     = blockIdx.y;            // 0..1
    const int tid   = threadIdx.x;           // 0..1023

    // ---- stage W as duplicated pairs ----
    #pragma unroll
    for (int idx = tid; idx < 64 * 48; idx += 1024) {
        const float v = Wg[idx];
        *(float2*)(Ws2 + idx * 2) = make_float2(v, v);
    }

    // ---- zero pads ----
    if (tid < 64) {
        xs[tid * 60 + 0]  = 0.0f;
        xs[tid * 60 + 57] = 0.0f;
        xs[tid * 60 + 58] = 0.0f;
        xs[tid * 60 + 59] = 0.0f;
        xs2[tid * 60 + 56] = 0.0f;
        xs2[tid * 60 + 57] = 0.0f;
        xs2[tid * 60 + 58] = 0.0f;
        xs2[tid * 60 + 59] = 0.0f;
    }

    // ---- stage x: one float4 per thread (64 rows x 14 quads); W-roll folded in.
    //      xs[i][u]=v with u = 1+((w+1)%56); xs2[i][u-1]=v keeps xs2[u]=xs[u+1].
    const float* xbase = x + (o * 64) * 3136 + n_src * 56;
    if (tid < 896) {
        const int i = tid / 14;
        const int q = tid - i * 14;
        const int w = q * 4;
        const float4 v = *(const float4*)(xbase + i * 3136 + w);
        float* row  = xs  + i * 60;
        float* row2 = xs2 + i * 60;
        int u0 = w + 2; if (u0 > 56) u0 -= 56;
        int u1 = w + 3; if (u1 > 56) u1 -= 56;
        int u2 = w + 4; if (u2 > 56) u2 -= 56;
        int u3 = w + 5; if (u3 > 56) u3 -= 56;
        row[u0] = v.x;  row[u1] = v.y;  row[u2] = v.z;  row[u3] = v.w;
        row2[u0 - 1] = v.x;  row2[u1 - 1] = v.y;  row2[u2 - 1] = v.z;  row2[u3 - 1] = v.w;
    }
    __syncthreads();

    // ---- compute: slice = tid>>7 covers i in [slice*8, slice*8+8).
    //      t128 = (g<<4)|k ; g<7 computes m = g*8 .. g*8+7; g==7 idle.
    const int slice = tid >> 7;
    const int t128  = tid & 127;
    const int k     = t128 & 15;
    const int g     = t128 >> 4;
    const int m0    = g * 8;
    const int i0    = slice * 8;
    const bool live = (g < 7);

    u64 acc01 = 0, acc23 = 0, acc45 = 0, acc67 = 0;

    if (live) {
        #pragma unroll
        for (int ii = 0; ii < 8; ii++) {
            const int i = i0 + ii;
            const u64* wp = (const u64*)(Ws2 + (i * 48 + k * 3) * 2);
            const u64 w0 = wp[0];
            const u64 w1 = wp[1];
            const u64 w2 = wp[2];

            const float* xr = xs + i * 60 + m0;     // 16B aligned
            const ulonglong2 P0 = *(const ulonglong2*)(xr);      // (xv0,xv1),(xv2,xv3)
            const ulonglong2 P1 = *(const ulonglong2*)(xr + 4);  // (xv4,xv5),(xv6,xv7)
            const u64        p4 = *(const u64*)(xr + 8);         // (xv8,xv9)
            const float* qr = xs2 + i * 60 + m0;
            const ulonglong2 Q0 = *(const ulonglong2*)(qr);      // (xv1,xv2),(xv3,xv4)
            const ulonglong2 Q1 = *(const ulonglong2*)(qr + 4);  // (xv5,xv6),(xv7,xv8)

            acc01 = ffma2(w0, P0.x, acc01);
            acc01 = ffma2(w1, Q0.x, acc01);
            acc01 = ffma2(w2, P0.y, acc01);

            acc23 = ffma2(w0, P0.y, acc23);
            acc23 = ffma2(w1, Q0.y, acc23);
            acc23 = ffma2(w2, P1.x, acc23);

            acc45 = ffma2(w0, P1.x, acc45);
            acc45 = ffma2(w1, Q1.x, acc45);
            acc45 = ffma2(w2, P1.y, acc45);

            acc67 = ffma2(w0, P1.y, acc67);
            acc67 = ffma2(w1, Q1.y, acc67);
            acc67 = ffma2(w2, p4,   acc67);
        }

        // spill all slices (stride 8 floats per a_idx, 16B aligned)
        const int a_idx = g * 16 + k;                 // 0..111
        u64* p = (u64*)ps + slice * PS_SLICE_U64 + a_idx * 4;
        ((ulonglong2*)p)[0] = make_ulonglong2(acc01, acc23);
        ((ulonglong2*)p)[1] = make_ulonglong2(acc45, acc67);
    }
    __syncthreads();

    // ---- reduce: 448 threads, each sums one float-pair over 8 slices ----
    if (tid < 448) {
        const int chunk = tid >> 2;                   // 0..111 == a_idx
        const int tp    = tid & 3;                    // which u64 pair of the 4
        const u64* base = (const u64*)ps + chunk * 4 + tp;
        u64 s = base[0];
        #pragma unroll
        for (int sl = 1; sl < 8; sl++)
            s = fadd2(s, base[sl * PS_SLICE_U64]);    // stride 448 u64 per slice

        const int kk = chunk & 15;
        const int gg = chunk >> 4;
        int n_out = n_src + 1;
        if (n_out == 56) n_out = 0;
        float* yp = y + (o * 16 + kk) * 3136 + n_out * 56 + gg * 8 + tp * 2;
        *(u64*)yp = s;
    }
}

extern "C" void kernel_launch(void* const* d_in, const int* in_sizes, int n_in,
                              void* d_out, int out_size)
{
    const float* x  = (const float*)d_in[0];   // (1,128,56,56) = 401408
    const float* Wg = (const float*)d_in[1];   // (64,16,3)     = 3072
    float* y = (float*)d_out;                  // (1,32,56,56)  = 100352

    static bool attr_set = false;
    if (!attr_set) {
        cudaFuncSetAttribute(shiftconv_kernel,
                             cudaFuncAttributeMaxDynamicSharedMemorySize,
                             SMEM_BYTES);
        attr_set = true;
    }

    dim3 grid(56, 2);
    shiftconv_kernel<<<grid, 1024, SMEM_BYTES>>>(x, Wg, y);
}